// round 6
// baseline (speedup 1.0000x reference)
#include <cuda_runtime.h>
#include <cuda_fp16.h>
#include <cstdint>

#define TOKENS 64
#define IN_F   8192
#define OUT_F  8192
#define NGROUPS 1024
#define KSPLIT 4
#define NBLK   64              // outputs per block

// K partition: tensor pipe takes groups [0, 688), SIMT fma pipe takes [688, 1024)
#define KT_TENSOR 344          // k16 tiles on HMMA path (5504 k)
#define KT_PER    (KT_TENSOR / KSPLIT)     // 86
#define G_SIMT0   688
#define G_SIMT    336          // groups on SIMT path (2688 k)
#define G_PER     (G_SIMT / KSPLIT)        // 84

// A fragments for HMMA: [kt][mt][lane] -> uint4
__device__ uint4 g_xa[512 * 4 * 32];                  // 1 MB (only kt<344 used)
// xh fp32, [token][k] for SIMT path
__device__ float g_xf[TOKENS * IN_F];                 // 2 MB
// partials: slices 0..3 = HMMA splits, 4..7 = SIMT splits
__device__ float g_part[2 * KSPLIT * TOKENS * OUT_F]; // 16 MB

#define INV_SQRT_8192 0.011048543456039806f

__device__ __forceinline__ int SW(int i) {
    return (i & ~31) | ((i ^ (i >> 5)) & 31);
}

#define FWHT_REG(a, N)                                            \
    _Pragma("unroll")                                             \
    for (int h = 1; h < (N); h <<= 1) {                           \
        _Pragma("unroll")                                         \
        for (int i = 0; i < (N); i++) {                           \
            if (!(i & h)) {                                       \
                float u = a[i], v = a[i ^ h];                     \
                a[i] = u + v; a[i ^ h] = u - v;                   \
            }                                                     \
        }                                                         \
    }

// ---------------------------------------------------------------------------
// Kernel A: FWHT(x*SU)*scale -> fp16 A-fragments (g_xa) + fp32 rows (g_xf).
// ---------------------------------------------------------------------------
__global__ __launch_bounds__(256) void fwht_in_kernel(
    const float* __restrict__ x,
    const float* __restrict__ SU,
    const float* __restrict__ Wscale)
{
    __shared__ float s[IN_F];
    const int t   = blockIdx.x;
    const int tid = threadIdx.x;
    const float* xr = x + (size_t)t * IN_F;

    float a[32];
#pragma unroll
    for (int j = 0; j < 32; j++) {
        const int idx = tid + 256 * j;
        a[j] = xr[idx] * SU[idx];
    }
    FWHT_REG(a, 32)
#pragma unroll
    for (int j = 0; j < 32; j++)
        s[SW(tid + 256 * j)] = a[j];
    __syncthreads();

    const int low = tid & 31;
    const int gb  = (tid >> 5) * 4;
    float b[4][8];
#pragma unroll
    for (int gg = 0; gg < 4; gg++)
#pragma unroll
        for (int j = 0; j < 8; j++)
            b[gg][j] = s[SW((gb + gg) * 256 + j * 32 + low)];
#pragma unroll
    for (int gg = 0; gg < 4; gg++) {
        FWHT_REG(b[gg], 8)
    }
    __syncthreads();
#pragma unroll
    for (int gg = 0; gg < 4; gg++)
#pragma unroll
        for (int j = 0; j < 8; j++)
            s[SW((gb + gg) * 256 + j * 32 + low)] = b[gg][j];
    __syncthreads();

    float c[32];
#pragma unroll
    for (int i = 0; i < 32; i++)
        c[i] = s[SW(tid * 32 + i)];
    FWHT_REG(c, 32)

    const float scale = INV_SQRT_8192 * Wscale[0];
#pragma unroll
    for (int i = 0; i < 32; i++) c[i] *= scale;

    // fp32 rows for SIMT path (contiguous, 8x STG.128)
    {
        float* dst = g_xf + (size_t)t * IN_F + tid * 32;
#pragma unroll
        for (int v = 0; v < 8; v++)
            *(float4*)(dst + v * 4) = make_float4(c[4*v], c[4*v+1], c[4*v+2], c[4*v+3]);
    }

    // fp16 A-fragment layout for HMMA path
    const int mt   = t >> 4;
    const int mrow = t & 15;
    uint32_t* xa = (uint32_t*)g_xa;
#pragma unroll
    for (int p = 0; p < 16; p++) {
        const int k0   = tid * 32 + 2 * p;
        const int kt   = k0 >> 4;
        const int r    = (k0 >> 3) & 1;
        const int lane = ((mrow & 7) << 2) | ((k0 >> 1) & 3);
        const int reg  = (r << 1) | (mrow >> 3);
        __half2 h = __floats2half2_rn(c[2 * p], c[2 * p + 1]);
        xa[(((kt * 4 + mt) * 32 + lane) << 2) + reg] = *(uint32_t*)&h;
    }
}

// ---------------------------------------------------------------------------
// Kernel B: dual-pipe GEMM. grid (128, 4), 256 threads.
//   warps 0-3: fp16 mma.sync on K [0, 5504)        (tensor pipe)
//   warps 4-7: f32x2 FFMA dot-products on K [5504, 8192)   (fma pipe)
// ---------------------------------------------------------------------------
__device__ __forceinline__ void mma16816(float c[4], const uint4& a,
                                         uint32_t b0, uint32_t b1)
{
    asm volatile(
        "mma.sync.aligned.m16n8k16.row.col.f32.f16.f16.f32 "
        "{%0,%1,%2,%3},{%4,%5,%6,%7},{%8,%9},{%0,%1,%2,%3};\n"
        : "+f"(c[0]), "+f"(c[1]), "+f"(c[2]), "+f"(c[3])
        : "r"(a.x), "r"(a.y), "r"(a.z), "r"(a.w), "r"(b0), "r"(b1));
}
__device__ __forceinline__ void ffma2(unsigned long long& d,
                                      unsigned long long a, unsigned long long b)
{
    asm("fma.rn.f32x2 %0, %1, %2, %0;" : "+l"(d) : "l"(a), "l"(b));
}
__device__ __forceinline__ unsigned long long pk2(float lo, float hi)
{
    unsigned long long r;
    asm("mov.b64 %0, {%1, %2};" : "=l"(r) : "f"(lo), "f"(hi));
    return r;
}

__global__ __launch_bounds__(256) void gemm_kernel(
    const int*   __restrict__ Qidxs,
    const float* __restrict__ grid)
{
    __shared__ uint32_t cb[256 * 4];               // fp16 half2 codebook (HMMA)
    __shared__ unsigned long long cbd[256 * 8];    // f32 {w,w} duplicated (SIMT)

    const int tid = threadIdx.x;
    // fill both codebooks (thread tid owns code tid)
    {
        const float4* g4 = (const float4*)grid;
        float4 lo = g4[tid * 2], hi = g4[tid * 2 + 1];
        __half2 h0 = __floats2half2_rn(lo.x, lo.y);
        __half2 h1 = __floats2half2_rn(lo.z, lo.w);
        __half2 h2 = __floats2half2_rn(hi.x, hi.y);
        __half2 h3 = __floats2half2_rn(hi.z, hi.w);
        cb[tid * 4 + 0] = *(uint32_t*)&h0;
        cb[tid * 4 + 1] = *(uint32_t*)&h1;
        cb[tid * 4 + 2] = *(uint32_t*)&h2;
        cb[tid * 4 + 3] = *(uint32_t*)&h3;
        const float w[8] = {lo.x, lo.y, lo.z, lo.w, hi.x, hi.y, hi.z, hi.w};
#pragma unroll
        for (int j = 0; j < 8; j++)
            cbd[tid * 8 + j] = pk2(w[j], w[j]);
    }
    __syncthreads();

    const int lane  = tid & 31;
    const int wid   = tid >> 5;
    const int oW    = blockIdx.x * NBLK;
    const int split = blockIdx.y;

    if (wid < 4) {
        // =================== HMMA path (R4 mainloop) ===================
        const int w  = wid;
        const int l4 = lane & 3;
        const int lq = lane >> 2;
        const int oT = oW + w * 16;
        const int ktBase = split * KT_PER;
        const int ktEnd  = ktBase + KT_PER;

        const int2* qp0 = (const int2*)(Qidxs + (size_t)(oT + lq) * NGROUPS);
        const int2* qp1 = (const int2*)(Qidxs + (size_t)(oT + 8 + lq) * NGROUPS);

        float acc[2][4][4];
#pragma unroll
        for (int n = 0; n < 2; n++)
#pragma unroll
            for (int m = 0; m < 4; m++)
#pragma unroll
                for (int r = 0; r < 4; r++) acc[n][m][r] = 0.0f;

        uint4 aB[2][4];
        int2  qB[2][2];
#pragma unroll
        for (int m = 0; m < 4; m++) {
            aB[0][m] = g_xa[((ktBase    ) * 4 + m) * 32 + lane];
            aB[1][m] = g_xa[((ktBase + 1) * 4 + m) * 32 + lane];
        }
        qB[0][0] = qp0[ktBase];     qB[0][1] = qp1[ktBase];
        qB[1][0] = qp0[ktBase + 1]; qB[1][1] = qp1[ktBase + 1];

        for (int kt = ktBase; kt < ktEnd; kt += 2) {
            {
                const uint32_t b00 = cb[(qB[0][0].x << 2) | l4];
                const uint32_t b01 = cb[(qB[0][0].y << 2) | l4];
                const uint32_t b10 = cb[(qB[0][1].x << 2) | l4];
                const uint32_t b11 = cb[(qB[0][1].y << 2) | l4];
#pragma unroll
                for (int m = 0; m < 4; m++) {
                    mma16816(acc[0][m], aB[0][m], b00, b01);
                    mma16816(acc[1][m], aB[0][m], b10, b11);
                }
                const int ktn = (kt + 2 < ktEnd) ? kt + 2 : ktEnd - 1;
#pragma unroll
                for (int m = 0; m < 4; m++)
                    aB[0][m] = g_xa[(ktn * 4 + m) * 32 + lane];
                qB[0][0] = qp0[ktn];
                qB[0][1] = qp1[ktn];
            }
            {
                const uint32_t b00 = cb[(qB[1][0].x << 2) | l4];
                const uint32_t b01 = cb[(qB[1][0].y << 2) | l4];
                const uint32_t b10 = cb[(qB[1][1].x << 2) | l4];
                const uint32_t b11 = cb[(qB[1][1].y << 2) | l4];
#pragma unroll
                for (int m = 0; m < 4; m++) {
                    mma16816(acc[0][m], aB[1][m], b00, b01);
                    mma16816(acc[1][m], aB[1][m], b10, b11);
                }
                const int ktn = (kt + 3 < ktEnd) ? kt + 3 : ktEnd - 1;
#pragma unroll
                for (int m = 0; m < 4; m++)
                    aB[1][m] = g_xa[(ktn * 4 + m) * 32 + lane];
                qB[1][0] = qp0[ktn];
                qB[1][1] = qp1[ktn];
            }
        }

        float* base = g_part + (size_t)split * TOKENS * OUT_F;
#pragma unroll
        for (int n = 0; n < 2; n++) {
            const int o = oT + n * 8 + 2 * l4;
#pragma unroll
            for (int m = 0; m < 4; m++) {
                const int t0 = m * 16 + lq;
                *(float2*)&base[(size_t)t0 * OUT_F + o] =
                    make_float2(acc[n][m][0], acc[n][m][1]);
                *(float2*)&base[(size_t)(t0 + 8) * OUT_F + o] =
                    make_float2(acc[n][m][2], acc[n][m][3]);
            }
        }
    } else {
        // =================== SIMT f32x2 path ===================
        const int wq = wid - 4;
        const int oS = oW + wq * 16;              // 16 outputs owned by warp
        const int t0 = 2 * lane;                  // 2 tokens per lane
        const int gBase = G_SIMT0 + split * G_PER;

        unsigned long long acc[16];
#pragma unroll
        for (int i = 0; i < 16; i++) acc[i] = 0ull;

        const float* r0 = g_xf + (size_t)t0 * IN_F;
        const float* r1 = r0 + IN_F;
        const ulonglong2* cbd2 = (const ulonglong2*)cbd;

        for (int gc = gBase; gc < gBase + G_PER; gc += 2) {
            // load x for 2 groups (16 k) x 2 tokens, pack into f32x2 pairs
            const float4* p0 = (const float4*)(r0 + gc * 8);
            const float4* p1 = (const float4*)(r1 + gc * 8);
            float4 a0 = p0[0], a1 = p0[1], a2 = p0[2], a3 = p0[3];
            float4 b0 = p1[0], b1 = p1[1], b2 = p1[2], b3 = p1[3];
            unsigned long long px[16];
            px[0]  = pk2(a0.x, b0.x); px[1]  = pk2(a0.y, b0.y);
            px[2]  = pk2(a0.z, b0.z); px[3]  = pk2(a0.w, b0.w);
            px[4]  = pk2(a1.x, b1.x); px[5]  = pk2(a1.y, b1.y);
            px[6]  = pk2(a1.z, b1.z); px[7]  = pk2(a1.w, b1.w);
            px[8]  = pk2(a2.x, b2.x); px[9]  = pk2(a2.y, b2.y);
            px[10] = pk2(a2.z, b2.z); px[11] = pk2(a2.w, b2.w);
            px[12] = pk2(a3.x, b3.x); px[13] = pk2(a3.y, b3.y);
            px[14] = pk2(a3.z, b3.z); px[15] = pk2(a3.w, b3.w);

#pragma unroll
            for (int i = 0; i < 16; i++) {
                const int2 q = *(const int2*)(Qidxs + (size_t)(oS + i) * NGROUPS + gc);
                const ulonglong2* cA = cbd2 + q.x * 4;
                const ulonglong2* cB = cbd2 + q.y * 4;
                ulonglong2 w0 = cA[0], w1 = cA[1], w2 = cA[2], w3 = cA[3];
                ffma2(acc[i], px[0], w0.x); ffma2(acc[i], px[1], w0.y);
                ffma2(acc[i], px[2], w1.x); ffma2(acc[i], px[3], w1.y);
                ffma2(acc[i], px[4], w2.x); ffma2(acc[i], px[5], w2.y);
                ffma2(acc[i], px[6], w3.x); ffma2(acc[i], px[7], w3.y);
                ulonglong2 v0 = cB[0], v1 = cB[1], v2 = cB[2], v3 = cB[3];
                ffma2(acc[i], px[8],  v0.x); ffma2(acc[i], px[9],  v0.y);
                ffma2(acc[i], px[10], v1.x); ffma2(acc[i], px[11], v1.y);
                ffma2(acc[i], px[12], v2.x); ffma2(acc[i], px[13], v2.y);
                ffma2(acc[i], px[14], v3.x); ffma2(acc[i], px[15], v3.y);
            }
        }

        // unpack + store: token t0 gets lo halves, t0+1 gets hi halves
        float lo[16], hi[16];
#pragma unroll
        for (int i = 0; i < 16; i++)
            asm("mov.b64 {%0, %1}, %2;" : "=f"(lo[i]), "=f"(hi[i]) : "l"(acc[i]));
        float* base = g_part + (size_t)(KSPLIT + split) * TOKENS * OUT_F;
        float* d0 = base + (size_t)t0 * OUT_F + oS;
        float* d1 = d0 + OUT_F;
#pragma unroll
        for (int v = 0; v < 4; v++) {
            *(float4*)(d0 + 4 * v) = make_float4(lo[4*v], lo[4*v+1], lo[4*v+2], lo[4*v+3]);
            *(float4*)(d1 + 4 * v) = make_float4(hi[4*v], hi[4*v+1], hi[4*v+2], hi[4*v+3]);
        }
    }
}

// ---------------------------------------------------------------------------
// Kernel C: sum 8 partials, FWHT, * SV/sqrt + bias. One block per token.
// ---------------------------------------------------------------------------
__global__ __launch_bounds__(256) void fwht_out_kernel(
    const float* __restrict__ SV,
    const float* __restrict__ bias,
    float* __restrict__ out)
{
    __shared__ float s[OUT_F];
    const int t   = blockIdx.x;
    const int tid = threadIdx.x;

    float a[32];
#pragma unroll
    for (int j = 0; j < 32; j++) {
        const int idx = tid + 256 * j;
        float v = 0.0f;
#pragma unroll
        for (int p = 0; p < 8; p++)
            v += g_part[(size_t)(p * TOKENS + t) * OUT_F + idx];
        a[j] = v;
    }
    FWHT_REG(a, 32)
#pragma unroll
    for (int j = 0; j < 32; j++)
        s[SW(tid + 256 * j)] = a[j];
    __syncthreads();

    const int low = tid & 31;
    const int gb  = (tid >> 5) * 4;
    float b[4][8];
#pragma unroll
    for (int gg = 0; gg < 4; gg++)
#pragma unroll
        for (int j = 0; j < 8; j++)
            b[gg][j] = s[SW((gb + gg) * 256 + j * 32 + low)];
#pragma unroll
    for (int gg = 0; gg < 4; gg++) {
        FWHT_REG(b[gg], 8)
    }
    __syncthreads();
#pragma unroll
    for (int gg = 0; gg < 4; gg++)
#pragma unroll
        for (int j = 0; j < 8; j++)
            s[SW((gb + gg) * 256 + j * 32 + low)] = b[gg][j];
    __syncthreads();

    float c[32];
#pragma unroll
    for (int i = 0; i < 32; i++)
        c[i] = s[SW(tid * 32 + i)];
    FWHT_REG(c, 32)

    float* orow = out + (size_t)t * OUT_F;
#pragma unroll
    for (int i = 0; i < 32; i++) {
        const int idx = tid * 32 + i;
        orow[idx] = c[i] * INV_SQRT_8192 * SV[idx] + bias[idx];
    }
}

// ---------------------------------------------------------------------------
// Inputs (metadata order): x, SU, SV, grid, Wscale, bias, Qidxs
// ---------------------------------------------------------------------------
extern "C" void kernel_launch(void* const* d_in, const int* in_sizes, int n_in,
                              void* d_out, int out_size)
{
    const float* x      = (const float*)d_in[0];
    const float* SU     = (const float*)d_in[1];
    const float* SV     = (const float*)d_in[2];
    const float* grid   = (const float*)d_in[3];
    const float* Wscale = (const float*)d_in[4];
    const float* bias   = (const float*)d_in[5];
    const int*   Qidxs  = (const int*)  d_in[6];
    float*       out    = (float*)d_out;

    fwht_in_kernel<<<TOKENS, 256>>>(x, SU, Wscale);
    dim3 ggrid(OUT_F / NBLK, KSPLIT);
    gemm_kernel<<<ggrid, 256>>>(Qidxs, grid);
    fwht_out_kernel<<<TOKENS, 256>>>(SV, bias, out);
}

// round 7
// speedup vs baseline: 3.5331x; 3.5331x over previous
#include <cuda_runtime.h>
#include <cuda_fp16.h>
#include <cstdint>

#define TOKENS 64
#define IN_F   8192
#define OUT_F  8192
#define NGROUPS (IN_F / 8)     // 1024
#define KT_TILES (IN_F / 16)   // 512 k16 tiles
#define KSPLIT 8
#define NBLK   64              // N per block (4 warps x N16)

// A fragments: [kt][mt][lane] -> uint4 (4 regs of m16k16 fp16 frag)
__device__ uint4 g_xa[KT_TILES * 4 * 32];            // 1 MB
// partial outputs per K-split: [split][token][out]
__device__ float g_part[KSPLIT * TOKENS * OUT_F];    // 16 MB

#define INV_SQRT_8192 0.011048543456039806f

// XOR bank swizzle on low 5 bits
__device__ __forceinline__ int SW(int i) {
    return (i & ~31) | ((i ^ (i >> 5)) & 31);
}

// in-register radix-2^L FWHT over array a[N]
#define FWHT_REG(a, N)                                            \
    _Pragma("unroll")                                             \
    for (int h = 1; h < (N); h <<= 1) {                           \
        _Pragma("unroll")                                         \
        for (int i = 0; i < (N); i++) {                           \
            if (!(i & h)) {                                       \
                float u = a[i], v = a[i ^ h];                     \
                a[i] = u + v; a[i ^ h] = u - v;                   \
            }                                                     \
        }                                                         \
    }

// ---------------------------------------------------------------------------
// Kernel A: FWHT(x*SU)*scale -> fp16, packed directly in mma A-fragment layout.
// One block per token, 256 threads, register-radix 32/8/32.
// ---------------------------------------------------------------------------
__global__ __launch_bounds__(256) void fwht_in_kernel(
    const float* __restrict__ x,
    const float* __restrict__ SU,
    const float* __restrict__ Wscale)
{
    __shared__ float s[IN_F];                 // 32 KB
    const int t   = blockIdx.x;
    const int tid = threadIdx.x;
    const float* xr = x + (size_t)t * IN_F;

    // phase A: stride-256 radix-32
    float a[32];
#pragma unroll
    for (int j = 0; j < 32; j++) {
        const int idx = tid + 256 * j;
        a[j] = xr[idx] * SU[idx];
    }
    FWHT_REG(a, 32)
#pragma unroll
    for (int j = 0; j < 32; j++)
        s[SW(tid + 256 * j)] = a[j];
    __syncthreads();

    // phase B: stride-32 radix-8, 4 groups per thread
    const int low = tid & 31;
    const int gb  = (tid >> 5) * 4;
    float b[4][8];
#pragma unroll
    for (int gg = 0; gg < 4; gg++)
#pragma unroll
        for (int j = 0; j < 8; j++)
            b[gg][j] = s[SW((gb + gg) * 256 + j * 32 + low)];
#pragma unroll
    for (int gg = 0; gg < 4; gg++) {
        FWHT_REG(b[gg], 8)
    }
    __syncthreads();
#pragma unroll
    for (int gg = 0; gg < 4; gg++)
#pragma unroll
        for (int j = 0; j < 8; j++)
            s[SW((gb + gg) * 256 + j * 32 + low)] = b[gg][j];
    __syncthreads();

    // phase C: contiguous radix-32 + epilogue pack
    float c[32];
#pragma unroll
    for (int i = 0; i < 32; i++)
        c[i] = s[SW(tid * 32 + i)];
    FWHT_REG(c, 32)

    const float scale = INV_SQRT_8192 * Wscale[0];
    const int mt   = t >> 4;
    const int mrow = t & 15;
    uint32_t* xa = (uint32_t*)g_xa;
#pragma unroll
    for (int p = 0; p < 16; p++) {
        const int k0   = tid * 32 + 2 * p;
        const int kt   = k0 >> 4;
        const int r    = (k0 >> 3) & 1;
        const int lane = ((mrow & 7) << 2) | ((k0 >> 1) & 3);
        const int reg  = (r << 1) | (mrow >> 3);
        __half2 h = __floats2half2_rn(c[2 * p] * scale, c[2 * p + 1] * scale);
        xa[(((kt * 4 + mt) * 32 + lane) << 2) + reg] = *(uint32_t*)&h;
    }
}

// ---------------------------------------------------------------------------
// Kernel B: fused codebook-decode + fp16 mma.sync GEMM.
// grid = (OUT_F/NBLK, KSPLIT). block = 128 (4 warps). warp = M64 x N16.
// Register prefetch distance 2 on both A frags and Qidxs.
// ---------------------------------------------------------------------------
__device__ __forceinline__ void mma16816(float c[4], const uint4& a,
                                         uint32_t b0, uint32_t b1)
{
    asm volatile(
        "mma.sync.aligned.m16n8k16.row.col.f32.f16.f16.f32 "
        "{%0,%1,%2,%3},{%4,%5,%6,%7},{%8,%9},{%0,%1,%2,%3};\n"
        : "+f"(c[0]), "+f"(c[1]), "+f"(c[2]), "+f"(c[3])
        : "r"(a.x), "r"(a.y), "r"(a.z), "r"(a.w), "r"(b0), "r"(b1));
}

__global__ __launch_bounds__(128) void gemm_kernel(
    const int*   __restrict__ Qidxs,
    const float* __restrict__ grid)
{
    __shared__ uint32_t cb[256 * 4];     // codebook as half2: [code][pair]
    const int tid = threadIdx.x;
    for (int i = tid; i < 1024; i += 128) {
        int c = i >> 2, j = i & 3;
        __half2 h = __floats2half2_rn(grid[c * 8 + 2 * j], grid[c * 8 + 2 * j + 1]);
        cb[i] = *(uint32_t*)&h;
    }
    __syncthreads();

    const int lane = tid & 31;
    const int w    = tid >> 5;
    const int l4   = lane & 3;
    const int lq   = lane >> 2;
    const int oW   = blockIdx.x * NBLK + w * 16;
    const int split = blockIdx.y;

    const int ktBase = split * (KT_TILES / KSPLIT);   // 64 tiles per split
    const int ktEnd  = ktBase + (KT_TILES / KSPLIT);

    const int2* qp0 = (const int2*)(Qidxs + (size_t)(oW + lq) * NGROUPS);
    const int2* qp1 = (const int2*)(Qidxs + (size_t)(oW + 8 + lq) * NGROUPS);

    float acc[2][4][4];
#pragma unroll
    for (int n = 0; n < 2; n++)
#pragma unroll
        for (int m = 0; m < 4; m++)
#pragma unroll
            for (int r = 0; r < 4; r++) acc[n][m][r] = 0.0f;

    // double-buffer, prefetch distance 2
    uint4 aB[2][4];
    int2  qB[2][2];
#pragma unroll
    for (int m = 0; m < 4; m++) {
        aB[0][m] = g_xa[((ktBase    ) * 4 + m) * 32 + lane];
        aB[1][m] = g_xa[((ktBase + 1) * 4 + m) * 32 + lane];
    }
    qB[0][0] = qp0[ktBase];     qB[0][1] = qp1[ktBase];
    qB[1][0] = qp0[ktBase + 1]; qB[1][1] = qp1[ktBase + 1];

    for (int kt = ktBase; kt < ktEnd; kt += 2) {
        // ---- sub-iter 0: consume buf0 (kt), refill with kt+2 ----
        {
            const uint32_t b00 = cb[(qB[0][0].x << 2) | l4];
            const uint32_t b01 = cb[(qB[0][0].y << 2) | l4];
            const uint32_t b10 = cb[(qB[0][1].x << 2) | l4];
            const uint32_t b11 = cb[(qB[0][1].y << 2) | l4];
#pragma unroll
            for (int m = 0; m < 4; m++) {
                mma16816(acc[0][m], aB[0][m], b00, b01);
                mma16816(acc[1][m], aB[0][m], b10, b11);
            }
            const int ktn = (kt + 2 < ktEnd) ? kt + 2 : ktEnd - 1;
#pragma unroll
            for (int m = 0; m < 4; m++)
                aB[0][m] = g_xa[(ktn * 4 + m) * 32 + lane];
            qB[0][0] = qp0[ktn];
            qB[0][1] = qp1[ktn];
        }
        // ---- sub-iter 1: consume buf1 (kt+1), refill with kt+3 ----
        {
            const uint32_t b00 = cb[(qB[1][0].x << 2) | l4];
            const uint32_t b01 = cb[(qB[1][0].y << 2) | l4];
            const uint32_t b10 = cb[(qB[1][1].x << 2) | l4];
            const uint32_t b11 = cb[(qB[1][1].y << 2) | l4];
#pragma unroll
            for (int m = 0; m < 4; m++) {
                mma16816(acc[0][m], aB[1][m], b00, b01);
                mma16816(acc[1][m], aB[1][m], b10, b11);
            }
            const int ktn = (kt + 3 < ktEnd) ? kt + 3 : ktEnd - 1;
#pragma unroll
            for (int m = 0; m < 4; m++)
                aB[1][m] = g_xa[(ktn * 4 + m) * 32 + lane];
            qB[1][0] = qp0[ktn];
            qB[1][1] = qp1[ktn];
        }
    }

    // store: C frag lane mapping -> t = mt*16 + lq (+8), o = oW + n*8 + 2*l4
    float* base = g_part + (size_t)split * TOKENS * OUT_F;
#pragma unroll
    for (int n = 0; n < 2; n++) {
        const int o = oW + n * 8 + 2 * l4;
#pragma unroll
        for (int m = 0; m < 4; m++) {
            const int t0 = m * 16 + lq;
            *(float2*)&base[(size_t)t0 * OUT_F + o] =
                make_float2(acc[n][m][0], acc[n][m][1]);
            *(float2*)&base[(size_t)(t0 + 8) * OUT_F + o] =
                make_float2(acc[n][m][2], acc[n][m][3]);
        }
    }
}

// ---------------------------------------------------------------------------
// Kernel C: sum KSPLIT partials, FWHT (register-radix), * SV/sqrt + bias.
// One block per token, 256 threads.
// ---------------------------------------------------------------------------
__global__ __launch_bounds__(256) void fwht_out_kernel(
    const float* __restrict__ SV,
    const float* __restrict__ bias,
    float* __restrict__ out)
{
    __shared__ float s[OUT_F];
    const int t   = blockIdx.x;
    const int tid = threadIdx.x;

    // phase A: stride-256 radix-32 (input = sum of 8 partials)
    float a[32];
#pragma unroll
    for (int j = 0; j < 32; j++) {
        const int idx = tid + 256 * j;
        float v0 = 0.0f, v1 = 0.0f;
#pragma unroll
        for (int p = 0; p < 8; p += 2) {
            v0 += g_part[(size_t)((p    ) * TOKENS + t) * OUT_F + idx];
            v1 += g_part[(size_t)((p + 1) * TOKENS + t) * OUT_F + idx];
        }
        a[j] = v0 + v1;
    }
    FWHT_REG(a, 32)
#pragma unroll
    for (int j = 0; j < 32; j++)
        s[SW(tid + 256 * j)] = a[j];
    __syncthreads();

    // phase B: stride-32 radix-8
    const int low = tid & 31;
    const int gb  = (tid >> 5) * 4;
    float b[4][8];
#pragma unroll
    for (int gg = 0; gg < 4; gg++)
#pragma unroll
        for (int j = 0; j < 8; j++)
            b[gg][j] = s[SW((gb + gg) * 256 + j * 32 + low)];
#pragma unroll
    for (int gg = 0; gg < 4; gg++) {
        FWHT_REG(b[gg], 8)
    }
    __syncthreads();
#pragma unroll
    for (int gg = 0; gg < 4; gg++)
#pragma unroll
        for (int j = 0; j < 8; j++)
            s[SW((gb + gg) * 256 + j * 32 + low)] = b[gg][j];
    __syncthreads();

    // phase C: contiguous radix-32 + epilogue
    float c[32];
#pragma unroll
    for (int i = 0; i < 32; i++)
        c[i] = s[SW(tid * 32 + i)];
    FWHT_REG(c, 32)

    float* orow = out + (size_t)t * OUT_F;
#pragma unroll
    for (int i = 0; i < 32; i++) {
        const int idx = tid * 32 + i;
        orow[idx] = c[i] * INV_SQRT_8192 * SV[idx] + bias[idx];
    }
}

// ---------------------------------------------------------------------------
// Inputs (metadata order): x, SU, SV, grid, Wscale, bias, Qidxs
// ---------------------------------------------------------------------------
extern "C" void kernel_launch(void* const* d_in, const int* in_sizes, int n_in,
                              void* d_out, int out_size)
{
    const float* x      = (const float*)d_in[0];
    const float* SU     = (const float*)d_in[1];
    const float* SV     = (const float*)d_in[2];
    const float* grid   = (const float*)d_in[3];
    const float* Wscale = (const float*)d_in[4];
    const float* bias   = (const float*)d_in[5];
    const int*   Qidxs  = (const int*)  d_in[6];
    float*       out    = (float*)d_out;

    fwht_in_kernel<<<TOKENS, 256>>>(x, SU, Wscale);
    dim3 ggrid(OUT_F / NBLK, KSPLIT);
    gemm_kernel<<<ggrid, 128>>>(Qidxs, grid);
    fwht_out_kernel<<<TOKENS, 256>>>(SV, bias, out);
}

// round 9
// speedup vs baseline: 4.0665x; 1.1510x over previous
#include <cuda_runtime.h>
#include <cuda_fp16.h>
#include <cstdint>

#define TOKENS 64
#define IN_F   8192
#define OUT_F  8192
#define NGROUPS (IN_F / 8)     // 1024
#define KT_TILES (IN_F / 16)   // 512 k16 tiles
#define KSPLIT 4
#define NBLK   64              // N per block (4 warps x N16)
#define HALF_F 4096

// A fragments: [kt][mt][lane] -> uint4 (4 regs of m16k16 fp16 frag)
__device__ uint4 g_xa[KT_TILES * 4 * 32];            // 1 MB
// partial outputs per K-split: [split][token][out]
__device__ float g_part[KSPLIT * TOKENS * OUT_F];    // 8 MB

#define INV_SQRT_8192 0.011048543456039806f

// XOR bank swizzle on low 5 bits
__device__ __forceinline__ int SW(int i) {
    return (i & ~31) | ((i ^ (i >> 5)) & 31);
}

// in-register radix-2^L FWHT over array a[N]
#define FWHT_REG(a, N)                                            \
    _Pragma("unroll")                                             \
    for (int h = 1; h < (N); h <<= 1) {                           \
        _Pragma("unroll")                                         \
        for (int i = 0; i < (N); i++) {                           \
            if (!(i & h)) {                                       \
                float u = a[i], v = a[i ^ h];                     \
                a[i] = u + v; a[i ^ h] = u - v;                   \
            }                                                     \
        }                                                         \
    }

// FWHT over 4096 elements held as: phase A (stride 256, radix 16),
// phase B (stride 16, radix 16), phase C (contiguous radix 16).
// 256 threads, 16 elems/thread, smem float s[4096].
// Caller supplies a[16] already holding elements tid + 256*j;
// result left in c[16] = contiguous block tid*16 .. tid*16+15.
#define FWHT4096_BODY(s, tid, a, c)                               \
    FWHT_REG(a, 16)                                               \
    _Pragma("unroll")                                             \
    for (int j = 0; j < 16; j++)                                  \
        s[SW(tid + 256 * j)] = a[j];                              \
    __syncthreads();                                              \
    {                                                             \
        const int lo = tid & 15, hi = tid >> 4;                   \
        float bb[16];                                             \
        _Pragma("unroll")                                         \
        for (int j = 0; j < 16; j++)                              \
            bb[j] = s[SW(hi * 256 + j * 16 + lo)];                \
        FWHT_REG(bb, 16)                                          \
        __syncthreads();                                          \
        _Pragma("unroll")                                         \
        for (int j = 0; j < 16; j++)                              \
            s[SW(hi * 256 + j * 16 + lo)] = bb[j];                \
    }                                                             \
    __syncthreads();                                              \
    _Pragma("unroll")                                             \
    for (int i = 0; i < 16; i++)                                  \
        c[i] = s[SW(tid * 16 + i)];                               \
    FWHT_REG(c, 16)

// ---------------------------------------------------------------------------
// Kernel A: FWHT(x*SU)*scale -> fp16 A-fragments. 2 blocks per token:
// stride-4096 butterfly folded into the load, FWHT_4096 per block.
// ---------------------------------------------------------------------------
__global__ __launch_bounds__(256) void fwht_in_kernel(
    const float* __restrict__ x,
    const float* __restrict__ SU,
    const float* __restrict__ Wscale)
{
    __shared__ float s[HALF_F];               // 16 KB
    const int t   = blockIdx.x >> 1;
    const int hb  = blockIdx.x & 1;
    const int tid = threadIdx.x;
    const float* xr = x + (size_t)t * IN_F;

    float a[16];
#pragma unroll
    for (int j = 0; j < 16; j++) {
        const int i = tid + 256 * j;
        const float v0 = xr[i] * SU[i];
        const float v1 = xr[i + HALF_F] * SU[i + HALF_F];
        a[j] = hb ? (v0 - v1) : (v0 + v1);
    }

    float c[16];
    FWHT4096_BODY(s, tid, a, c)

    const float scale = INV_SQRT_8192 * Wscale[0];
    const int mt   = t >> 4;
    const int mrow = t & 15;
    const int kt   = hb * 256 + tid;          // this thread's k16 tile
    uint32_t* xa = (uint32_t*)g_xa;
#pragma unroll
    for (int p = 0; p < 8; p++) {
        const int r    = p >> 2;
        const int lane = ((mrow & 7) << 2) | (p & 3);
        const int reg  = (r << 1) | (mrow >> 3);
        __half2 h = __floats2half2_rn(c[2 * p] * scale, c[2 * p + 1] * scale);
        xa[(((kt * 4 + mt) * 32 + lane) << 2) + reg] = *(uint32_t*)&h;
    }
}

// ---------------------------------------------------------------------------
// Kernel B: fused codebook-decode + fp16 mma.sync GEMM (R4 mainloop).
// grid = (OUT_F/NBLK, KSPLIT). block = 128 (4 warps). warp = M64 x N16.
// ---------------------------------------------------------------------------
__device__ __forceinline__ void mma16816(float c[4], const uint4& a,
                                         uint32_t b0, uint32_t b1)
{
    asm volatile(
        "mma.sync.aligned.m16n8k16.row.col.f32.f16.f16.f32 "
        "{%0,%1,%2,%3},{%4,%5,%6,%7},{%8,%9},{%0,%1,%2,%3};\n"
        : "+f"(c[0]), "+f"(c[1]), "+f"(c[2]), "+f"(c[3])
        : "r"(a.x), "r"(a.y), "r"(a.z), "r"(a.w), "r"(b0), "r"(b1));
}

__global__ __launch_bounds__(128) void gemm_kernel(
    const int*   __restrict__ Qidxs,
    const float* __restrict__ grid)
{
    __shared__ uint32_t cb[256 * 4];     // codebook as half2: [code][pair]
    const int tid = threadIdx.x;
    for (int i = tid; i < 1024; i += 128) {
        int c = i >> 2, j = i & 3;
        __half2 h = __floats2half2_rn(grid[c * 8 + 2 * j], grid[c * 8 + 2 * j + 1]);
        cb[i] = *(uint32_t*)&h;
    }
    __syncthreads();

    const int lane = tid & 31;
    const int w    = tid >> 5;
    const int l4   = lane & 3;
    const int lq   = lane >> 2;
    const int oW   = blockIdx.x * NBLK + w * 16;
    const int split = blockIdx.y;

    const int ktBase = split * (KT_TILES / KSPLIT);   // 128 tiles per split
    const int ktEnd  = ktBase + (KT_TILES / KSPLIT);

    const int2* qp0 = (const int2*)(Qidxs + (size_t)(oW + lq) * NGROUPS);
    const int2* qp1 = (const int2*)(Qidxs + (size_t)(oW + 8 + lq) * NGROUPS);

    float acc[2][4][4];
#pragma unroll
    for (int n = 0; n < 2; n++)
#pragma unroll
        for (int m = 0; m < 4; m++)
#pragma unroll
            for (int r = 0; r < 4; r++) acc[n][m][r] = 0.0f;

    uint4 aB[2][4];
    int2  qB[2][2];
#pragma unroll
    for (int m = 0; m < 4; m++) {
        aB[0][m] = g_xa[((ktBase    ) * 4 + m) * 32 + lane];
        aB[1][m] = g_xa[((ktBase + 1) * 4 + m) * 32 + lane];
    }
    qB[0][0] = qp0[ktBase];     qB[0][1] = qp1[ktBase];
    qB[1][0] = qp0[ktBase + 1]; qB[1][1] = qp1[ktBase + 1];

    for (int kt = ktBase; kt < ktEnd; kt += 2) {
        {
            const uint32_t b00 = cb[(qB[0][0].x << 2) | l4];
            const uint32_t b01 = cb[(qB[0][0].y << 2) | l4];
            const uint32_t b10 = cb[(qB[0][1].x << 2) | l4];
            const uint32_t b11 = cb[(qB[0][1].y << 2) | l4];
#pragma unroll
            for (int m = 0; m < 4; m++) {
                mma16816(acc[0][m], aB[0][m], b00, b01);
                mma16816(acc[1][m], aB[0][m], b10, b11);
            }
            const int ktn = (kt + 2 < ktEnd) ? kt + 2 : ktEnd - 1;
#pragma unroll
            for (int m = 0; m < 4; m++)
                aB[0][m] = g_xa[(ktn * 4 + m) * 32 + lane];
            qB[0][0] = qp0[ktn];
            qB[0][1] = qp1[ktn];
        }
        {
            const uint32_t b00 = cb[(qB[1][0].x << 2) | l4];
            const uint32_t b01 = cb[(qB[1][0].y << 2) | l4];
            const uint32_t b10 = cb[(qB[1][1].x << 2) | l4];
            const uint32_t b11 = cb[(qB[1][1].y << 2) | l4];
#pragma unroll
            for (int m = 0; m < 4; m++) {
                mma16816(acc[0][m], aB[1][m], b00, b01);
                mma16816(acc[1][m], aB[1][m], b10, b11);
            }
            const int ktn = (kt + 3 < ktEnd) ? kt + 3 : ktEnd - 1;
#pragma unroll
            for (int m = 0; m < 4; m++)
                aB[1][m] = g_xa[(ktn * 4 + m) * 32 + lane];
            qB[1][0] = qp0[ktn];
            qB[1][1] = qp1[ktn];
        }
    }

    float* base = g_part + (size_t)split * TOKENS * OUT_F;
#pragma unroll
    for (int n = 0; n < 2; n++) {
        const int o = oW + n * 8 + 2 * l4;
#pragma unroll
        for (int m = 0; m < 4; m++) {
            const int t0 = m * 16 + lq;
            *(float2*)&base[(size_t)t0 * OUT_F + o] =
                make_float2(acc[n][m][0], acc[n][m][1]);
            *(float2*)&base[(size_t)(t0 + 8) * OUT_F + o] =
                make_float2(acc[n][m][2], acc[n][m][3]);
        }
    }
}

// ---------------------------------------------------------------------------
// Kernel C: sum KSPLIT partials (with folded stride-4096 butterfly),
// FWHT_4096, * SV/sqrt + bias. 2 blocks per token.
// ---------------------------------------------------------------------------
__global__ __launch_bounds__(256) void fwht_out_kernel(
    const float* __restrict__ SV,
    const float* __restrict__ bias,
    float* __restrict__ out)
{
    __shared__ float s[HALF_F];
    const int t   = blockIdx.x >> 1;
    const int hb  = blockIdx.x & 1;
    const int tid = threadIdx.x;

    float a[16];
#pragma unroll
    for (int j = 0; j < 16; j++) {
        const int i = tid + 256 * j;
        float v0 = 0.0f, v1 = 0.0f;
#pragma unroll
        for (int p = 0; p < KSPLIT; p++) {
            const float* row = g_part + (size_t)(p * TOKENS + t) * OUT_F;
            v0 += row[i];
            v1 += row[i + HALF_F];
        }
        a[j] = hb ? (v0 - v1) : (v0 + v1);
    }

    float c[16];
    FWHT4096_BODY(s, tid, a, c)

    float* orow = out + (size_t)t * OUT_F + hb * HALF_F;
#pragma unroll
    for (int i = 0; i < 16; i++) {
        const int idx = tid * 16 + i;
        const int gidx = hb * HALF_F + idx;
        orow[idx] = c[i] * INV_SQRT_8192 * SV[gidx] + bias[gidx];
    }
}

// ---------------------------------------------------------------------------
// Inputs (metadata order): x, SU, SV, grid, Wscale, bias, Qidxs
// ---------------------------------------------------------------------------
extern "C" void kernel_launch(void* const* d_in, const int* in_sizes, int n_in,
                              void* d_out, int out_size)
{
    const float* x      = (const float*)d_in[0];
    const float* SU     = (const float*)d_in[1];
    const float* SV     = (const float*)d_in[2];
    const float* grid   = (const float*)d_in[3];
    const float* Wscale = (const float*)d_in[4];
    const float* bias   = (const float*)d_in[5];
    const int*   Qidxs  = (const int*)  d_in[6];
    float*       out    = (float*)d_out;

    fwht_in_kernel<<<2 * TOKENS, 256>>>(x, SU, Wscale);
    dim3 ggrid(OUT_F / NBLK, KSPLIT);
    gemm_kernel<<<ggrid, 128>>>(Qidxs, grid);
    fwht_out_kernel<<<2 * TOKENS, 256>>>(SV, bias, out);
}

// round 10
// speedup vs baseline: 4.1272x; 1.0149x over previous
#include <cuda_runtime.h>
#include <cuda_fp16.h>
#include <cstdint>

#define TOKENS 64
#define IN_F   8192
#define OUT_F  8192
#define NGROUPS (IN_F / 8)     // 1024
#define KT_TILES (IN_F / 16)   // 512 k16 tiles
#define KSPLIT 4
#define NBLK   64              // N per block (4 warps x N16)
#define HALF_F 4096

// A fragments: [kt][mt][lane] -> uint4 (4 regs of m16k16 fp16 frag)
__device__ uint4 g_xa[KT_TILES * 4 * 32];            // 1 MB
// partial outputs per K-split: [split][token][out]
__device__ float g_part[KSPLIT * TOKENS * OUT_F];    // 8 MB

#define INV_SQRT_8192 0.011048543456039806f

// XOR bank swizzle on low 5 bits
__device__ __forceinline__ int SW(int i) {
    return (i & ~31) | ((i ^ (i >> 5)) & 31);
}

// in-register radix-2^L FWHT over array a[N]
#define FWHT_REG(a, N)                                            \
    _Pragma("unroll")                                             \
    for (int h = 1; h < (N); h <<= 1) {                           \
        _Pragma("unroll")                                         \
        for (int i = 0; i < (N); i++) {                           \
            if (!(i & h)) {                                       \
                float u = a[i], v = a[i ^ h];                     \
                a[i] = u + v; a[i ^ h] = u - v;                   \
            }                                                     \
        }                                                         \
    }

// FWHT over 4096 elements: phase A (stride 256, radix 16),
// phase B (stride 16, radix 16), phase C (contiguous radix 16).
// 256 threads, 16 elems/thread, smem float s[4096].
#define FWHT4096_BODY(s, tid, a, c)                               \
    FWHT_REG(a, 16)                                               \
    _Pragma("unroll")                                             \
    for (int j = 0; j < 16; j++)                                  \
        s[SW(tid + 256 * j)] = a[j];                              \
    __syncthreads();                                              \
    {                                                             \
        const int lo = tid & 15, hi = tid >> 4;                   \
        float bb[16];                                             \
        _Pragma("unroll")                                         \
        for (int j = 0; j < 16; j++)                              \
            bb[j] = s[SW(hi * 256 + j * 16 + lo)];                \
        FWHT_REG(bb, 16)                                          \
        __syncthreads();                                          \
        _Pragma("unroll")                                         \
        for (int j = 0; j < 16; j++)                              \
            s[SW(hi * 256 + j * 16 + lo)] = bb[j];                \
    }                                                             \
    __syncthreads();                                              \
    _Pragma("unroll")                                             \
    for (int i = 0; i < 16; i++)                                  \
        c[i] = s[SW(tid * 16 + i)];                               \
    FWHT_REG(c, 16)

// ---------------------------------------------------------------------------
// Kernel A: FWHT(x*SU)*scale -> fp16 A-fragments. 2 blocks per token.
// Triggers programmatic launch completion for the gemm.
// ---------------------------------------------------------------------------
__global__ __launch_bounds__(256) void fwht_in_kernel(
    const float* __restrict__ x,
    const float* __restrict__ SU,
    const float* __restrict__ Wscale)
{
    __shared__ float s[HALF_F];               // 16 KB
    const int t   = blockIdx.x >> 1;
    const int hb  = blockIdx.x & 1;
    const int tid = threadIdx.x;
    const float* xr = x + (size_t)t * IN_F;

    float a[16];
#pragma unroll
    for (int j = 0; j < 16; j++) {
        const int i = tid + 256 * j;
        const float v0 = xr[i] * SU[i];
        const float v1 = xr[i + HALF_F] * SU[i + HALF_F];
        a[j] = hb ? (v0 - v1) : (v0 + v1);
    }

    float c[16];
    FWHT4096_BODY(s, tid, a, c)

    const float scale = INV_SQRT_8192 * Wscale[0];
    const int mt   = t >> 4;
    const int mrow = t & 15;
    const int kt   = hb * 256 + tid;          // this thread's k16 tile
    uint32_t* xa = (uint32_t*)g_xa;
#pragma unroll
    for (int p = 0; p < 8; p++) {
        const int r    = p >> 2;
        const int lane = ((mrow & 7) << 2) | (p & 3);
        const int reg  = (r << 1) | (mrow >> 3);
        __half2 h = __floats2half2_rn(c[2 * p] * scale, c[2 * p + 1] * scale);
        xa[(((kt * 4 + mt) * 32 + lane) << 2) + reg] = *(uint32_t*)&h;
    }

    cudaTriggerProgrammaticLaunchCompletion();
}

// ---------------------------------------------------------------------------
// Kernel B: fused codebook-decode + fp16 mma.sync GEMM.
// PDL: codebook fill + Qidxs prefetch run before the grid-dependency sync;
// g_xa reads only after it.
// ---------------------------------------------------------------------------
__device__ __forceinline__ void mma16816(float c[4], const uint4& a,
                                         uint32_t b0, uint32_t b1)
{
    asm volatile(
        "mma.sync.aligned.m16n8k16.row.col.f32.f16.f16.f32 "
        "{%0,%1,%2,%3},{%4,%5,%6,%7},{%8,%9},{%0,%1,%2,%3};\n"
        : "+f"(c[0]), "+f"(c[1]), "+f"(c[2]), "+f"(c[3])
        : "r"(a.x), "r"(a.y), "r"(a.z), "r"(a.w), "r"(b0), "r"(b1));
}

__global__ __launch_bounds__(128) void gemm_kernel(
    const int*   __restrict__ Qidxs,
    const float* __restrict__ grid)
{
    __shared__ uint32_t cb[256 * 4];     // codebook as half2: [code][pair]
    const int tid = threadIdx.x;
    // prologue (independent of fwht_in): codebook convert + store
    for (int i = tid; i < 1024; i += 128) {
        int c = i >> 2, j = i & 3;
        __half2 h = __floats2half2_rn(grid[c * 8 + 2 * j], grid[c * 8 + 2 * j + 1]);
        cb[i] = *(uint32_t*)&h;
    }

    const int lane = tid & 31;
    const int w    = tid >> 5;
    const int l4   = lane & 3;
    const int lq   = lane >> 2;
    const int oW   = blockIdx.x * NBLK + w * 16;
    const int split = blockIdx.y;

    const int ktBase = split * (KT_TILES / KSPLIT);   // 128 tiles per split
    const int ktEnd  = ktBase + (KT_TILES / KSPLIT);

    const int2* qp0 = (const int2*)(Qidxs + (size_t)(oW + lq) * NGROUPS);
    const int2* qp1 = (const int2*)(Qidxs + (size_t)(oW + 8 + lq) * NGROUPS);

    // Qidxs prefetch (input tensor — also independent of fwht_in)
    int2 qB[2][2];
    qB[0][0] = qp0[ktBase];     qB[0][1] = qp1[ktBase];
    qB[1][0] = qp0[ktBase + 1]; qB[1][1] = qp1[ktBase + 1];

    float acc[2][4][4];
#pragma unroll
    for (int n = 0; n < 2; n++)
#pragma unroll
        for (int m = 0; m < 4; m++)
#pragma unroll
            for (int r = 0; r < 4; r++) acc[n][m][r] = 0.0f;

    __syncthreads();                       // cb visible

    // wait for fwht_in's g_xa before first A-fragment load
    cudaGridDependencySynchronize();

    uint4 aB[2][4];
#pragma unroll
    for (int m = 0; m < 4; m++) {
        aB[0][m] = g_xa[((ktBase    ) * 4 + m) * 32 + lane];
        aB[1][m] = g_xa[((ktBase + 1) * 4 + m) * 32 + lane];
    }

    for (int kt = ktBase; kt < ktEnd; kt += 2) {
        {
            const uint32_t b00 = cb[(qB[0][0].x << 2) | l4];
            const uint32_t b01 = cb[(qB[0][0].y << 2) | l4];
            const uint32_t b10 = cb[(qB[0][1].x << 2) | l4];
            const uint32_t b11 = cb[(qB[0][1].y << 2) | l4];
#pragma unroll
            for (int m = 0; m < 4; m++) {
                mma16816(acc[0][m], aB[0][m], b00, b01);
                mma16816(acc[1][m], aB[0][m], b10, b11);
            }
            const int ktn = (kt + 2 < ktEnd) ? kt + 2 : ktEnd - 1;
#pragma unroll
            for (int m = 0; m < 4; m++)
                aB[0][m] = g_xa[(ktn * 4 + m) * 32 + lane];
            qB[0][0] = qp0[ktn];
            qB[0][1] = qp1[ktn];
        }
        {
            const uint32_t b00 = cb[(qB[1][0].x << 2) | l4];
            const uint32_t b01 = cb[(qB[1][0].y << 2) | l4];
            const uint32_t b10 = cb[(qB[1][1].x << 2) | l4];
            const uint32_t b11 = cb[(qB[1][1].y << 2) | l4];
#pragma unroll
            for (int m = 0; m < 4; m++) {
                mma16816(acc[0][m], aB[1][m], b00, b01);
                mma16816(acc[1][m], aB[1][m], b10, b11);
            }
            const int ktn = (kt + 3 < ktEnd) ? kt + 3 : ktEnd - 1;
#pragma unroll
            for (int m = 0; m < 4; m++)
                aB[1][m] = g_xa[(ktn * 4 + m) * 32 + lane];
            qB[1][0] = qp0[ktn];
            qB[1][1] = qp1[ktn];
        }
    }

    float* base = g_part + (size_t)split * TOKENS * OUT_F;
#pragma unroll
    for (int n = 0; n < 2; n++) {
        const int o = oW + n * 8 + 2 * l4;
#pragma unroll
        for (int m = 0; m < 4; m++) {
            const int t0 = m * 16 + lq;
            *(float2*)&base[(size_t)t0 * OUT_F + o] =
                make_float2(acc[n][m][0], acc[n][m][1]);
            *(float2*)&base[(size_t)(t0 + 8) * OUT_F + o] =
                make_float2(acc[n][m][2], acc[n][m][3]);
        }
    }

    cudaTriggerProgrammaticLaunchCompletion();
}

// ---------------------------------------------------------------------------
// Kernel C: sum KSPLIT partials (with folded stride-4096 butterfly),
// FWHT_4096, * SV/sqrt + bias. 2 blocks per token. PDL consumer.
// ---------------------------------------------------------------------------
__global__ __launch_bounds__(256) void fwht_out_kernel(
    const float* __restrict__ SV,
    const float* __restrict__ bias,
    float* __restrict__ out)
{
    __shared__ float s[HALF_F];
    const int t   = blockIdx.x >> 1;
    const int hb  = blockIdx.x & 1;
    const int tid = threadIdx.x;

    // wait for gemm partials
    cudaGridDependencySynchronize();

    float a[16];
#pragma unroll
    for (int j = 0; j < 16; j++) {
        const int i = tid + 256 * j;
        float v0 = 0.0f, v1 = 0.0f;
#pragma unroll
        for (int p = 0; p < KSPLIT; p++) {
            const float* row = g_part + (size_t)(p * TOKENS + t) * OUT_F;
            v0 += row[i];
            v1 += row[i + HALF_F];
        }
        a[j] = hb ? (v0 - v1) : (v0 + v1);
    }

    float c[16];
    FWHT4096_BODY(s, tid, a, c)

    float* orow = out + (size_t)t * OUT_F + hb * HALF_F;
#pragma unroll
    for (int i = 0; i < 16; i++) {
        const int idx = tid * 16 + i;
        const int gidx = hb * HALF_F + idx;
        orow[idx] = c[i] * INV_SQRT_8192 * SV[gidx] + bias[gidx];
    }
}

// ---------------------------------------------------------------------------
// Inputs (metadata order): x, SU, SV, grid, Wscale, bias, Qidxs
// ---------------------------------------------------------------------------
extern "C" void kernel_launch(void* const* d_in, const int* in_sizes, int n_in,
                              void* d_out, int out_size)
{
    const float* x      = (const float*)d_in[0];
    const float* SU     = (const float*)d_in[1];
    const float* SV     = (const float*)d_in[2];
    const float* grid   = (const float*)d_in[3];
    const float* Wscale = (const float*)d_in[4];
    const float* bias   = (const float*)d_in[5];
    const int*   Qidxs  = (const int*)  d_in[6];
    float*       out    = (float*)d_out;

    // kernel 1: plain launch
    fwht_in_kernel<<<2 * TOKENS, 256>>>(x, SU, Wscale);

    // kernel 2: PDL launch (overlaps prologue with fwht_in tail)
    {
        cudaLaunchConfig_t cfg = {};
        cfg.gridDim  = dim3(OUT_F / NBLK, KSPLIT, 1);
        cfg.blockDim = dim3(128, 1, 1);
        cudaLaunchAttribute attr[1];
        attr[0].id = cudaLaunchAttributeProgrammaticStreamSerialization;
        attr[0].val.programmaticStreamSerializationAllowed = 1;
        cfg.attrs = attr;
        cfg.numAttrs = 1;
        cudaLaunchKernelEx(&cfg, gemm_kernel, Qidxs, grid);
    }

    // kernel 3: PDL launch (overlaps launch/setup with gemm tail)
    {
        cudaLaunchConfig_t cfg = {};
        cfg.gridDim  = dim3(2 * TOKENS, 1, 1);
        cfg.blockDim = dim3(256, 1, 1);
        cudaLaunchAttribute attr[1];
        attr[0].id = cudaLaunchAttributeProgrammaticStreamSerialization;
        attr[0].val.programmaticStreamSerializationAllowed = 1;
        cfg.attrs = attr;
        cfg.numAttrs = 1;
        cudaLaunchKernelEx(&cfg, fwht_out_kernel, SV, bias, out);
    }
}